// round 3
// baseline (speedup 1.0000x reference)
#include <cuda_runtime.h>

#define HH 256
#define WW 256
#define BB 16
#define CIN 32
#define COUT 32
#define KM 16

// Scratch (static __device__ arrays: allocation-free per harness rules)
__device__ float g_Dr[HH], g_Di[HH];          // Dirichlet kernel D(h)
__device__ float g_tc[KM * WW];               // cos(2*pi*c*w/256)
__device__ float g_ts[KM * WW];               // sin(2*pi*c*w/256)
__device__ float g_Sre[BB * CIN * KM], g_Sim[BB * CIN * KM];
__device__ float g_Pre[BB * COUT * KM * WW], g_Pim[BB * COUT * KM * WW];

// ---------------------------------------------------------------------------
// K0: trig tables + Dirichlet kernel
// ---------------------------------------------------------------------------
__global__ void k0_tables() {
    int t = blockIdx.x * blockDim.x + threadIdx.x; // 0..4095
    if (t < KM * WW) {
        int c = t >> 8, w = t & 255;
        float s, cc;
        sincospif((float)(c * w) / 128.0f, &s, &cc);
        g_tc[t] = cc;
        g_ts[t] = s;
    }
    if (t < HH) {
        float dr = 0.f, di = 0.f;
#pragma unroll
        for (int r = 0; r < KM; r++) {
            float s, cc;
            sincospif((float)(r * t) / 128.0f, &s, &cc);
            dr += cc;
            di -= s;   // D(h) = sum e^{-2pi i r h/256}
        }
        g_Dr[t] = dr;
        g_Di[t] = di;
    }
}

// ---------------------------------------------------------------------------
// K1: x (B,Cin,H,W) -> S[b,c,col] = (1/256) * sum_w e^{-2pi i col w/256} * y[w]
//     y[w] = sum_h D(h) x[h,w].   One block per (b,c). Streams all of x once.
// ---------------------------------------------------------------------------
__global__ __launch_bounds__(256) void k1_S(const float* __restrict__ x) {
    int bc = blockIdx.x;       // b*CIN + c
    int w  = threadIdx.x;      // 0..255

    __shared__ float sDr[HH], sDi[HH];
    __shared__ float syre[WW], syim[WW];
    sDr[w] = g_Dr[w];
    sDi[w] = g_Di[w];
    __syncthreads();

    const float* xp = x + (size_t)bc * HH * WW + w;
    float yre = 0.f, yim = 0.f;
#pragma unroll 8
    for (int h = 0; h < HH; h++) {
        float v = xp[(size_t)h * WW];
        yre = fmaf(sDr[h], v, yre);
        yim = fmaf(sDi[h], v, yim);
    }
    syre[w] = yre;
    syim[w] = yim;
    __syncthreads();

    // 8 warps, each warp handles cols {warp, warp+8}
    int warp = w >> 5, lane = w & 31;
    for (int cc = warp; cc < KM; cc += 8) {
        float are = 0.f, aim = 0.f;
        for (int j = lane; j < WW; j += 32) {
            float c = g_tc[cc * WW + j], s = g_ts[cc * WW + j];
            float yr = syre[j], yi = syim[j];
            // y * e^{-i phi}: re = yr*c + yi*s ; im = yi*c - yr*s
            are = fmaf(yr, c, are);  are = fmaf(yi, s, are);
            aim = fmaf(yi, c, aim);  aim = fmaf(-yr, s, aim);
        }
#pragma unroll
        for (int off = 16; off; off >>= 1) {
            are += __shfl_down_sync(0xffffffffu, are, off);
            aim += __shfl_down_sync(0xffffffffu, aim, off);
        }
        if (lane == 0) {
            g_Sre[bc * KM + cc] = are * (1.0f / 256.0f);
            g_Sim[bc * KM + cc] = aim * (1.0f / 256.0f);
        }
    }
}

// ---------------------------------------------------------------------------
// K2: blk[b,o,r,c] = sum_i S[b,i,r]*w[i,o,r,c]  (complex), then
//     P[b,o,r,w]  = sum_c (alpha_c/256)*blk[r,c]*e^{+2pi i c w/256}
//     One block per (b,o).
// ---------------------------------------------------------------------------
__global__ __launch_bounds__(256) void k2_P(const float* __restrict__ wr,
                                            const float* __restrict__ wi) {
    int bo = blockIdx.x;       // b*COUT + o
    int b  = bo >> 5, o = bo & 31;
    int t  = threadIdx.x;      // 0..255

    __shared__ float sSre[CIN * KM], sSim[CIN * KM];   // [i][r]  (512 each)
    __shared__ float sBre[KM * KM],  sBim[KM * KM];    // [r][c], pre-scaled

    // FIX (R2): CIN*KM = 512 > blockDim = 256 -> must stride
    for (int idx = t; idx < CIN * KM; idx += 256) {
        sSre[idx] = g_Sre[b * CIN * KM + idx];
        sSim[idx] = g_Sim[b * CIN * KM + idx];
    }
    __syncthreads();

    // blk: thread = r*16 + c
    {
        int r = t >> 4, c = t & 15;
        float bre = 0.f, bim = 0.f;
        for (int i = 0; i < CIN; i++) {
            float sre = sSre[i * KM + r], sim = sSim[i * KM + r];
            size_t widx = (((size_t)i * COUT + o) * KM + r) * KM + c;
            float wre = wr[widx], wim = wi[widx];
            bre = fmaf(sre, wre, bre);  bre = fmaf(-sim, wim, bre);
            bim = fmaf(sre, wim, bim);  bim = fmaf(sim, wre, bim);
        }
        float a = (c == 0 ? 1.0f : 2.0f) * (1.0f / 256.0f);
        sBre[t] = bre * a;
        sBim[t] = bim * a;
    }
    __syncthreads();

    // P: thread = w, loop r. Trig values for this w live in registers.
    int w = t;
    float tcr[KM], tsr[KM];
#pragma unroll
    for (int c = 0; c < KM; c++) {
        tcr[c] = g_tc[c * WW + w];
        tsr[c] = g_ts[c * WW + w];
    }
#pragma unroll
    for (int r = 0; r < KM; r++) {
        float pre = 0.f, pim = 0.f;
#pragma unroll
        for (int c = 0; c < KM; c++) {
            float bre = sBre[r * KM + c], bim = sBim[r * KM + c];
            // blk * e^{+i phi}
            pre = fmaf(bre, tcr[c], pre);  pre = fmaf(-bim, tsr[c], pre);
            pim = fmaf(bre, tsr[c], pim);  pim = fmaf(bim, tcr[c], pim);
        }
        g_Pre[((size_t)bo * KM + r) * WW + w] = pre;
        g_Pim[((size_t)bo * KM + r) * WW + w] = pim;
    }
}

// ---------------------------------------------------------------------------
// K3: out[b,o,h,w] = sum_r ( ReP[r,w]*cos(2pi r h/256) - ImP[r,w]*sin(...) )
//     h-fold: out[h] = A - B, out[256-h] = A + B. One block per (b,o),
//     thread = w, P held in registers, trig table broadcast from smem.
// ---------------------------------------------------------------------------
__global__ __launch_bounds__(256) void k3_out(float* __restrict__ out) {
    int bo = blockIdx.x;
    int w  = threadIdx.x;

    // strig[h][0..15] = cos(2pi r h/256), strig[h][16..31] = sin(...)
    __shared__ float strig[129 * 32];
    for (int idx = w; idx < 129 * KM; idx += 256) {
        int h = idx >> 4, r = idx & 15;
        float s, c;
        sincospif((float)(r * h) / 128.0f, &s, &c);
        strig[h * 32 + r]      = c;
        strig[h * 32 + 16 + r] = s;
    }

    float pre[KM], pim[KM];
#pragma unroll
    for (int r = 0; r < KM; r++) {
        pre[r] = g_Pre[((size_t)bo * KM + r) * WW + w];
        pim[r] = g_Pim[((size_t)bo * KM + r) * WW + w];
    }
    __syncthreads();

    float* op = out + (size_t)bo * HH * WW + w;
    for (int h = 0; h <= 128; h++) {
        const float4* tg4 = (const float4*)&strig[h * 32];
        float A = 0.f, Bv = 0.f;
#pragma unroll
        for (int q = 0; q < 4; q++) {
            float4 tc = tg4[q];
            float4 ts = tg4[q + 4];
            A  = fmaf(pre[q * 4 + 0], tc.x, A);
            A  = fmaf(pre[q * 4 + 1], tc.y, A);
            A  = fmaf(pre[q * 4 + 2], tc.z, A);
            A  = fmaf(pre[q * 4 + 3], tc.w, A);
            Bv = fmaf(pim[q * 4 + 0], ts.x, Bv);
            Bv = fmaf(pim[q * 4 + 1], ts.y, Bv);
            Bv = fmaf(pim[q * 4 + 2], ts.z, Bv);
            Bv = fmaf(pim[q * 4 + 3], ts.w, Bv);
        }
        op[(size_t)h * WW] = A - Bv;
        if (h >= 1 && h <= 127) op[(size_t)(256 - h) * WW] = A + Bv;
    }
}

// ---------------------------------------------------------------------------
extern "C" void kernel_launch(void* const* d_in, const int* in_sizes, int n_in,
                              void* d_out, int out_size) {
    const float* x  = (const float*)d_in[0];
    const float* wr = (const float*)d_in[1];
    const float* wi = (const float*)d_in[2];
    float* out = (float*)d_out;

    k0_tables<<<16, 256>>>();
    k1_S<<<BB * CIN, 256>>>(x);
    k2_P<<<BB * COUT, 256>>>(wr, wi);
    k3_out<<<BB * COUT, 256>>>(out);
}

// round 4
// speedup vs baseline: 1.2370x; 1.2370x over previous
#include <cuda_runtime.h>

#define HH 256
#define WW 256
#define BB 16
#define CIN 32
#define COUT 32
#define KM 16

// Scratch (static __device__ arrays: allocation-free per harness rules)
__device__ float g_Dr[HH], g_Di[HH];          // Dirichlet kernel D(h)
__device__ float g_tc[KM * WW];               // cos(2*pi*c*w/256)
__device__ float g_ts[KM * WW];               // sin(2*pi*c*w/256)
__device__ float g_Sre[BB * CIN * KM], g_Sim[BB * CIN * KM];

// ---------------------------------------------------------------------------
// K0: trig tables + Dirichlet kernel
// ---------------------------------------------------------------------------
__global__ void k0_tables() {
    int t = blockIdx.x * blockDim.x + threadIdx.x; // 0..4095
    if (t < KM * WW) {
        int c = t >> 8, w = t & 255;
        float s, cc;
        sincospif((float)(c * w) / 128.0f, &s, &cc);
        g_tc[t] = cc;
        g_ts[t] = s;
    }
    if (t < HH) {
        float dr = 0.f, di = 0.f;
#pragma unroll
        for (int r = 0; r < KM; r++) {
            float s, cc;
            sincospif((float)(r * t) / 128.0f, &s, &cc);
            dr += cc;
            di -= s;   // D(h) = sum e^{-2pi i r h/256}
        }
        g_Dr[t] = dr;
        g_Di[t] = di;
    }
}

// ---------------------------------------------------------------------------
// K1: x (B,Cin,H,W) -> S[b,c,col] = (1/256) * sum_w e^{-2pi i col w/256} * y[w]
//     y[w] = sum_h D(h) x[h,w].   One block per (b,c). Streams all of x once.
// ---------------------------------------------------------------------------
__global__ __launch_bounds__(256) void k1_S(const float* __restrict__ x) {
    int bc = blockIdx.x;       // b*CIN + c
    int w  = threadIdx.x;      // 0..255

    __shared__ float sDr[HH], sDi[HH];
    __shared__ float syre[WW], syim[WW];
    sDr[w] = g_Dr[w];
    sDi[w] = g_Di[w];
    __syncthreads();

    const float* xp = x + (size_t)bc * HH * WW + w;
    float yre = 0.f, yim = 0.f;
#pragma unroll 16
    for (int h = 0; h < HH; h++) {
        float v = xp[(size_t)h * WW];
        yre = fmaf(sDr[h], v, yre);
        yim = fmaf(sDi[h], v, yim);
    }
    syre[w] = yre;
    syim[w] = yim;
    __syncthreads();

    // 8 warps, each warp handles cols {warp, warp+8}
    int warp = w >> 5, lane = w & 31;
    for (int cc = warp; cc < KM; cc += 8) {
        float are = 0.f, aim = 0.f;
        for (int j = lane; j < WW; j += 32) {
            float c = g_tc[cc * WW + j], s = g_ts[cc * WW + j];
            float yr = syre[j], yi = syim[j];
            // y * e^{-i phi}: re = yr*c + yi*s ; im = yi*c - yr*s
            are = fmaf(yr, c, are);  are = fmaf(yi, s, are);
            aim = fmaf(yi, c, aim);  aim = fmaf(-yr, s, aim);
        }
#pragma unroll
        for (int off = 16; off; off >>= 1) {
            are += __shfl_down_sync(0xffffffffu, are, off);
            aim += __shfl_down_sync(0xffffffffu, aim, off);
        }
        if (lane == 0) {
            g_Sre[bc * KM + cc] = are * (1.0f / 256.0f);
            g_Sim[bc * KM + cc] = aim * (1.0f / 256.0f);
        }
    }
}

// ---------------------------------------------------------------------------
// K23 (fused): per block bo = b*COUT+o
//   Phase A: blk[r,c] = sum_i S[b,i,r]*w[i,o,r,c]  (complex, pre-scaled)
//   Phase B: P[r] per thread w:  P[r,w] = sum_c blk[r,c]*e^{+2pi i c w/256}
//            (kept entirely in registers — no global round trip)
//   Phase C: out[h,w] = sum_r ReP[r,w]*cos(2pi r h/256) - ImP[r,w]*sin(...)
//            4-way h-fold via r-parity split:
//              cos[128-h,r] = (-1)^r cos[h,r];  sin[128-h,r] = -(-1)^r sin[h,r]
//            out[h]     = (Ae+Ao) - (Be+Bo)
//            out[256-h] = (Ae+Ao) + (Be+Bo)
//            out[128-h] = (Ae-Ao) + (Be-Bo)
//            out[128+h] = (Ae-Ao) - (Be-Bo)
// ---------------------------------------------------------------------------
__global__ __launch_bounds__(256, 4) void k23(const float* __restrict__ wr,
                                              const float* __restrict__ wi,
                                              float* __restrict__ out) {
    int bo = blockIdx.x;       // b*COUT + o
    int b  = bo >> 5, o = bo & 31;
    int t  = threadIdx.x;      // 0..255

    __shared__ float  sSre[CIN * KM], sSim[CIN * KM];  // [i][r]
    __shared__ float2 sB[KM * KM];                     // [r][c] (re,im), pre-scaled
    __shared__ float  strig[65 * 32];                  // [h][0..15]=cos, [16..31]=sin

    for (int idx = t; idx < CIN * KM; idx += 256) {
        sSre[idx] = g_Sre[b * CIN * KM + idx];
        sSim[idx] = g_Sim[b * CIN * KM + idx];
    }
    for (int idx = t; idx < 65 * KM; idx += 256) {
        int h = idx >> 4, r = idx & 15;
        float s, c;
        sincospif((float)(r * h) / 128.0f, &s, &c);
        strig[h * 32 + r]      = c;
        strig[h * 32 + 16 + r] = s;
    }
    __syncthreads();

    // Phase A: blk, thread = r*16 + c
    {
        int r = t >> 4, c = t & 15;
        float bre = 0.f, bim = 0.f;
        for (int i = 0; i < CIN; i++) {
            float sre = sSre[i * KM + r], sim = sSim[i * KM + r];
            size_t widx = (((size_t)i * COUT + o) * KM + r) * KM + c;
            float wre = wr[widx], wim = wi[widx];
            bre = fmaf(sre, wre, bre);  bre = fmaf(-sim, wim, bre);
            bim = fmaf(sre, wim, bim);  bim = fmaf(sim, wre, bim);
        }
        float a = (c == 0 ? 1.0f : 2.0f) * (1.0f / 256.0f);
        sB[t] = make_float2(bre * a, bim * a);
    }
    __syncthreads();

    // Phase B: P[r] in registers, thread = w; c outer so trig stays in regs
    int w = t;
    float pre[KM], pim[KM];
#pragma unroll
    for (int r = 0; r < KM; r++) { pre[r] = 0.f; pim[r] = 0.f; }
#pragma unroll
    for (int c = 0; c < KM; c++) {
        float tc = g_tc[c * WW + w], ts = g_ts[c * WW + w];
#pragma unroll
        for (int r = 0; r < KM; r++) {
            float2 bv = sB[r * KM + c];
            // blk * e^{+i phi}
            pre[r] = fmaf(bv.x, tc, pre[r]);  pre[r] = fmaf(-bv.y, ts, pre[r]);
            pim[r] = fmaf(bv.x, ts, pim[r]);  pim[r] = fmaf(bv.y, tc, pim[r]);
        }
    }

    // Phase C: 4-way folded inverse h-DFT
    float* op = out + (size_t)bo * HH * WW + w;
    for (int h = 0; h <= 64; h++) {
        const float4* tg4 = (const float4*)&strig[h * 32];
        float Ae = 0.f, Ao = 0.f, Be = 0.f, Bo = 0.f;
#pragma unroll
        for (int q = 0; q < 4; q++) {
            float4 tc = tg4[q];
            float4 ts = tg4[q + 4];
            Ae = fmaf(pre[4 * q + 0], tc.x, Ae);
            Ao = fmaf(pre[4 * q + 1], tc.y, Ao);
            Ae = fmaf(pre[4 * q + 2], tc.z, Ae);
            Ao = fmaf(pre[4 * q + 3], tc.w, Ao);
            Be = fmaf(pim[4 * q + 0], ts.x, Be);
            Bo = fmaf(pim[4 * q + 1], ts.y, Bo);
            Be = fmaf(pim[4 * q + 2], ts.z, Be);
            Bo = fmaf(pim[4 * q + 3], ts.w, Bo);
        }
        float Apl = Ae + Ao, Ami = Ae - Ao;
        float Bpl = Be + Bo, Bmi = Be - Bo;
        op[(size_t)h * WW]         = Apl - Bpl;   // h
        op[(size_t)(128 - h) * WW] = Ami + Bmi;   // 128-h
        if (h >= 1) {
            op[(size_t)(256 - h) * WW] = Apl + Bpl;   // 256-h
            op[(size_t)(128 + h) * WW] = Ami - Bmi;   // 128+h
        }
    }
}

// ---------------------------------------------------------------------------
extern "C" void kernel_launch(void* const* d_in, const int* in_sizes, int n_in,
                              void* d_out, int out_size) {
    const float* x  = (const float*)d_in[0];
    const float* wr = (const float*)d_in[1];
    const float* wi = (const float*)d_in[2];
    float* out = (float*)d_out;

    k0_tables<<<16, 256>>>();
    k1_S<<<BB * CIN, 256>>>(x);
    k23<<<BB * COUT, 256>>>(wr, wi, out);
}

// round 5
// speedup vs baseline: 1.3295x; 1.0747x over previous
#include <cuda_runtime.h>

#define HH 256
#define WW 256
#define BB 16
#define CIN 32
#define COUT 32
#define KM 16

// S handoff between k1 and k23 (allocation-free scratch)
__device__ float g_Sre[BB * CIN * KM], g_Sim[BB * CIN * KM];

// Packed f32x2 FMA: d = a*b + c elementwise on {lo,hi} fp32 pairs (FFMA2)
#define FMA2(d, a, b, c) \
    asm("fma.rn.f32x2 %0, %1, %2, %3;" : "=l"(d) : "l"(a), "l"(b), "l"(c))

__device__ __forceinline__ unsigned long long pack2(float lo, float hi) {
    unsigned long long d;
    asm("mov.b64 %0, {%1, %2};" : "=l"(d) : "f"(lo), "f"(hi));
    return d;
}
__device__ __forceinline__ void unpack2(unsigned long long v, float& lo, float& hi) {
    asm("mov.b64 {%0, %1}, %2;" : "=f"(lo), "=f"(hi) : "l"(v));
}

// ---------------------------------------------------------------------------
// K1: x (B,Cin,H,W) -> S[b,c,col] = (1/256) * sum_w e^{-2pi i col w/256} * y[w]
//     y[w] = sum_h D(h) x[h,w],  D(h) = sum_{r<16} e^{-2pi i r h/256}.
//     One block per (b,c). Self-contained: D and twiddles computed inline.
// ---------------------------------------------------------------------------
__global__ __launch_bounds__(256) void k1_S(const float* __restrict__ x) {
    int bc = blockIdx.x;       // b*CIN + c
    int w  = threadIdx.x;      // 0..255

    __shared__ float2 sD[HH];            // {Dr, Di}
    __shared__ float  syre[WW], syim[WW];

    // Dirichlet kernel for h = w (this thread's index)
    {
        float dr = 0.f, di = 0.f;
#pragma unroll
        for (int r = 0; r < KM; r++) {
            float s, c;
            sincospif((float)(r * w) / 128.0f, &s, &c);
            dr += c;
            di -= s;
        }
        sD[w] = make_float2(dr, di);
    }
    __syncthreads();

    // Stream this (b,c) image: packed {yre,yim} accumulation
    const float* xp = x + (size_t)bc * HH * WW + w;
    unsigned long long Y = 0ULL;
#pragma unroll 16
    for (int h = 0; h < HH; h++) {
        float v = xp[(size_t)h * WW];
        unsigned long long vv = pack2(v, v);
        unsigned long long D  = *reinterpret_cast<const unsigned long long*>(&sD[h]);
        FMA2(Y, vv, D, Y);
    }
    float yre, yim;
    unpack2(Y, yre, yim);
    syre[w] = yre;
    syim[w] = yim;
    __syncthreads();

    // 8 warps, each warp handles cols {warp, warp+8}; twiddles on the fly
    int warp = w >> 5, lane = w & 31;
    for (int cc = warp; cc < KM; cc += 8) {
        float are = 0.f, aim = 0.f;
#pragma unroll
        for (int it = 0; it < 8; it++) {
            int j = lane + it * 32;
            float s, c;
            sincospif((float)(cc * j) / 128.0f, &s, &c);
            float yr = syre[j], yi = syim[j];
            // y * e^{-i phi}: re = yr*c + yi*s ; im = yi*c - yr*s
            are = fmaf(yr, c, are);  are = fmaf(yi, s, are);
            aim = fmaf(yi, c, aim);  aim = fmaf(-yr, s, aim);
        }
#pragma unroll
        for (int off = 16; off; off >>= 1) {
            are += __shfl_down_sync(0xffffffffu, are, off);
            aim += __shfl_down_sync(0xffffffffu, aim, off);
        }
        if (lane == 0) {
            g_Sre[bc * KM + cc] = are * (1.0f / 256.0f);
            g_Sim[bc * KM + cc] = aim * (1.0f / 256.0f);
        }
    }
}

// ---------------------------------------------------------------------------
// K23 (fused): per block bo = b*COUT+o
//   Phase A: blk[r,c] = sum_i S[b,i,r]*w[i,o,r,c]  (complex, pre-scaled);
//            stored packed as {bre,bre} and {-bim,bim} for f32x2 phase B.
//   Phase B: pp[r] = {ReP, ImP},  P[r,w] = sum_c blk[r,c]*e^{+2pi i c w/256}
//            (registers only; twiddles via sincospif per c)
//   Phase C: out[h,w] = sum_r ReP[r]*cos(2pi r h/256) - ImP[r]*sin(...)
//            4-way h-fold via r-parity split, packed {A,B} accumulators.
// ---------------------------------------------------------------------------
__global__ __launch_bounds__(256, 4) void k23(const float* __restrict__ wr,
                                              const float* __restrict__ wi,
                                              float* __restrict__ out) {
    int bo = blockIdx.x;       // b*COUT + o
    int b  = bo >> 5, o = bo & 31;
    int t  = threadIdx.x;      // 0..255

    __shared__ float  sSre[CIN * KM], sSim[CIN * KM];  // [i][r]
    __shared__ float2 sBxx[KM * KM];                   // [r][c] {bre,bre} scaled
    __shared__ float2 sByy[KM * KM];                   // [r][c] {-bim,bim} scaled
    __shared__ float2 strig2[65 * KM];                 // [h][r] {cos, sin}

    for (int idx = t; idx < CIN * KM; idx += 256) {
        sSre[idx] = g_Sre[b * CIN * KM + idx];
        sSim[idx] = g_Sim[b * CIN * KM + idx];
    }
    for (int idx = t; idx < 65 * KM; idx += 256) {
        int h = idx >> 4, r = idx & 15;
        float s, c;
        sincospif((float)(r * h) / 128.0f, &s, &c);
        strig2[idx] = make_float2(c, s);
    }
    __syncthreads();

    // Phase A: blk, thread = r*16 + c
    {
        int r = t >> 4, c = t & 15;
        float bre = 0.f, bim = 0.f;
        for (int i = 0; i < CIN; i++) {
            float sre = sSre[i * KM + r], sim = sSim[i * KM + r];
            size_t widx = (((size_t)i * COUT + o) * KM + r) * KM + c;
            float wre = wr[widx], wim = wi[widx];
            bre = fmaf(sre, wre, bre);  bre = fmaf(-sim, wim, bre);
            bim = fmaf(sre, wim, bim);  bim = fmaf(sim, wre, bim);
        }
        float a = (c == 0 ? 1.0f : 2.0f) * (1.0f / 256.0f);
        bre *= a;
        bim *= a;
        sBxx[t] = make_float2(bre, bre);
        sByy[t] = make_float2(-bim, bim);
    }
    __syncthreads();

    // Phase B: packed pp[r] = {ReP, ImP}, thread = w; c outer, r inner
    int w = t;
    unsigned long long pp[KM];
#pragma unroll
    for (int r = 0; r < KM; r++) pp[r] = 0ULL;
#pragma unroll
    for (int c = 0; c < KM; c++) {
        float s, cv;
        sincospif((float)(c * w) / 128.0f, &s, &cv);
        unsigned long long P1 = pack2(cv, s);   // {tc, ts}
        unsigned long long P2 = pack2(s, cv);   // {ts, tc}
#pragma unroll
        for (int r = 0; r < KM; r++) {
            unsigned long long xx = *reinterpret_cast<const unsigned long long*>(&sBxx[r * KM + c]);
            unsigned long long yy = *reinterpret_cast<const unsigned long long*>(&sByy[r * KM + c]);
            // {pre,pim} += {bre,bre}*{tc,ts}  then  += {-bim,bim}*{ts,tc}
            FMA2(pp[r], xx, P1, pp[r]);
            FMA2(pp[r], yy, P2, pp[r]);
        }
    }

    // Phase C: 4-way folded inverse h-DFT with packed {A,B} accumulators
    float* op = out + (size_t)bo * HH * WW + w;
    for (int h = 0; h <= 64; h++) {
        const ulonglong2* tg = reinterpret_cast<const ulonglong2*>(&strig2[h * KM]);
        unsigned long long AeBe = 0ULL, AoBo = 0ULL;
#pragma unroll
        for (int q = 0; q < 8; q++) {
            ulonglong2 tv = tg[q];            // .x = {cos,sin} of r=2q ; .y = r=2q+1
            FMA2(AeBe, pp[2 * q],     tv.x, AeBe);
            FMA2(AoBo, pp[2 * q + 1], tv.y, AoBo);
        }
        float Ae, Be, Ao, Bo;
        unpack2(AeBe, Ae, Be);
        unpack2(AoBo, Ao, Bo);
        float Apl = Ae + Ao, Ami = Ae - Ao;
        float Bpl = Be + Bo, Bmi = Be - Bo;
        op[(size_t)h * WW]         = Apl - Bpl;   // h
        op[(size_t)(128 - h) * WW] = Ami + Bmi;   // 128-h
        if (h >= 1) {
            op[(size_t)(256 - h) * WW] = Apl + Bpl;   // 256-h
            op[(size_t)(128 + h) * WW] = Ami - Bmi;   // 128+h
        }
    }
}

// ---------------------------------------------------------------------------
extern "C" void kernel_launch(void* const* d_in, const int* in_sizes, int n_in,
                              void* d_out, int out_size) {
    const float* x  = (const float*)d_in[0];
    const float* wr = (const float*)d_in[1];
    const float* wi = (const float*)d_in[2];
    float* out = (float*)d_out;

    k1_S<<<BB * CIN, 256>>>(x);
    k23<<<BB * COUT, 256>>>(wr, wi, out);
}

// round 8
// speedup vs baseline: 1.3854x; 1.0421x over previous
#include <cuda_runtime.h>
#include <utility>

#define HH 256
#define WW 256
#define BB 16
#define CIN 32
#define COUT 32
#define KM 16

// S handoff between k1 and k23 (allocation-free scratch)
__device__ float g_Sre[BB * CIN * KM], g_Sim[BB * CIN * KM];

// Packed f32x2 FMA: d = a*b + c elementwise on {lo,hi} fp32 pairs (FFMA2)
#define FMA2(d, a, b, c) \
    asm("fma.rn.f32x2 %0, %1, %2, %3;" : "=l"(d) : "l"(a), "l"(b), "l"(c))

__device__ __forceinline__ unsigned long long pack2(float lo, float hi) {
    unsigned long long d;
    asm("mov.b64 %0, {%1, %2};" : "=l"(d) : "f"(lo), "f"(hi));
    return d;
}
__device__ __forceinline__ void unpack2(unsigned long long v, float& lo, float& hi) {
    asm("mov.b64 {%0, %1}, %2;" : "=f"(lo), "=f"(hi) : "l"(v));
}

// ---------------------------------------------------------------------------
// Compile-time trig: cos/sin(pi*m/128) with exact integer range reduction
// to [0, pi/2] and a degree-15/14 Taylor (error ~1e-11). All values become
// FFMA 32-bit immediates after expansion.
// ---------------------------------------------------------------------------
constexpr __host__ __device__ double tp_sin(double x) {
    double x2 = x * x, t = x, s = x;
    t *= -x2 / 6.0;   s += t;
    t *= -x2 / 20.0;  s += t;
    t *= -x2 / 42.0;  s += t;
    t *= -x2 / 72.0;  s += t;
    t *= -x2 / 110.0; s += t;
    t *= -x2 / 156.0; s += t;
    t *= -x2 / 210.0; s += t;
    return s;
}
constexpr __host__ __device__ double tp_cos(double x) {
    double x2 = x * x, t = 1.0, s = 1.0;
    t *= -x2 / 2.0;   s += t;
    t *= -x2 / 12.0;  s += t;
    t *= -x2 / 30.0;  s += t;
    t *= -x2 / 56.0;  s += t;
    t *= -x2 / 90.0;  s += t;
    t *= -x2 / 132.0; s += t;
    t *= -x2 / 182.0; s += t;
    return s;
}
constexpr double C_PI = 3.14159265358979323846264338327950288;

constexpr __host__ __device__ float ccosm(int m) {   // cos(pi*m/128)
    m &= 255;
    double sgn = 1.0;
    if (m > 128) m = 256 - m;                   // cos(2pi-x)=cos x
    if (m > 64) { sgn = -1.0; m = 128 - m; }    // cos(pi-x)=-cos x
    if (m == 64) return 0.0f;                   // exact pi/2
    return (float)(sgn * tp_cos(C_PI * m / 128.0));
}
constexpr __host__ __device__ float csinm(int m) {   // sin(pi*m/128)
    m &= 255;
    double sgn = 1.0;
    if (m > 128) { sgn = -1.0; m = 256 - m; }   // sin(2pi-x)=-sin x
    if (m > 64) m = 128 - m;                    // sin(pi-x)=sin x
    if (m == 0) return 0.0f;
    return (float)(sgn * tp_sin(C_PI * m / 128.0));
}
// Dirichlet kernel D(h) = sum_{r<16} e^{-i pi r h/128}
constexpr __host__ __device__ float cDr(int h) {
    double s = 0.0;
    for (int r = 0; r < KM; r++) s += (double)ccosm(r * h);
    return (float)s;
}
constexpr __host__ __device__ float cDi(int h) {
    double s = 0.0;
    for (int r = 0; r < KM; r++) s -= (double)csinm(r * h);
    return (float)s;
}

// ---------------------------------------------------------------------------
// K1: x (B,Cin,H,W) -> S[b,c,col] = (1/256) * sum_w e^{-2pi i col w/256} * y[w]
//     y[w] = sum_h D(h) x[h,w].  D(h) baked as FFMA immediates via fold
//     expansion (instantiation depth 1); 8 rotating accumulators keep MLP high.
// ---------------------------------------------------------------------------
template <int H>
__device__ __forceinline__ void k1_one(const float* __restrict__ xp, float* acc) {
    float v = xp[(size_t)H * WW];
    constexpr float dr = cDr(H);
    constexpr float di = cDi(H);
    acc[2 * (H & 3) + 0] = fmaf(v, dr, acc[2 * (H & 3) + 0]);
    acc[2 * (H & 3) + 1] = fmaf(v, di, acc[2 * (H & 3) + 1]);
}
template <int... Hs>
__device__ __forceinline__ void k1_all(const float* __restrict__ xp, float* acc,
                                       std::integer_sequence<int, Hs...>) {
    (k1_one<Hs>(xp, acc), ...);
}

__global__ __launch_bounds__(256) void k1_S(const float* __restrict__ x) {
    int bc = blockIdx.x;       // b*CIN + c
    int w  = threadIdx.x;      // 0..255

    __shared__ float syre[WW], syim[WW];

    const float* xp = x + (size_t)bc * HH * WW + w;
    float acc[8] = {0.f, 0.f, 0.f, 0.f, 0.f, 0.f, 0.f, 0.f};
    k1_all(xp, acc, std::make_integer_sequence<int, HH>{});
    syre[w] = (acc[0] + acc[2]) + (acc[4] + acc[6]);
    syim[w] = (acc[1] + acc[3]) + (acc[5] + acc[7]);
    __syncthreads();

    // 8 warps, each warp handles cols {warp, warp+8}; twiddles on the fly
    int warp = w >> 5, lane = w & 31;
    for (int cc = warp; cc < KM; cc += 8) {
        float are = 0.f, aim = 0.f;
#pragma unroll
        for (int it = 0; it < 8; it++) {
            int j = lane + it * 32;
            float s, c;
            sincospif((float)(cc * j) / 128.0f, &s, &c);
            float yr = syre[j], yi = syim[j];
            // y * e^{-i phi}: re = yr*c + yi*s ; im = yi*c - yr*s
            are = fmaf(yr, c, are);  are = fmaf(yi, s, are);
            aim = fmaf(yi, c, aim);  aim = fmaf(-yr, s, aim);
        }
#pragma unroll
        for (int off = 16; off; off >>= 1) {
            are += __shfl_down_sync(0xffffffffu, are, off);
            aim += __shfl_down_sync(0xffffffffu, aim, off);
        }
        if (lane == 0) {
            g_Sre[bc * KM + cc] = are * (1.0f / 256.0f);
            g_Sim[bc * KM + cc] = aim * (1.0f / 256.0f);
        }
    }
}

// ---------------------------------------------------------------------------
// K23 phase C body for one h: fully unrolled, trig as FFMA immediates.
//   out[h]     = (Ae+Ao) - (Be+Bo)     out[256-h] = (Ae+Ao) + (Be+Bo)
//   out[128-h] = (Ae-Ao) + (Be-Bo)     out[128+h] = (Ae-Ao) - (Be-Bo)
// ---------------------------------------------------------------------------
template <int H, int R>
__device__ __forceinline__ void k3_step(const float* pre, const float* pim,
                                        float& Ae, float& Ao, float& Be, float& Bo) {
    constexpr float cv = ccosm(R * H);
    constexpr float sv = csinm(R * H);
    if constexpr ((R & 1) != 0) {
        Ao = fmaf(pre[R], cv, Ao);
        Bo = fmaf(pim[R], sv, Bo);
    } else {
        Ae = fmaf(pre[R], cv, Ae);
        Be = fmaf(pim[R], sv, Be);
    }
}

template <int H, int... Rs>
__device__ __forceinline__ void k3_one(const float* pre, const float* pim,
                                       float* __restrict__ op,
                                       std::integer_sequence<int, Rs...>) {
    float Ae = 0.f, Ao = 0.f, Be = 0.f, Bo = 0.f;
    (k3_step<H, Rs>(pre, pim, Ae, Ao, Be, Bo), ...);
    float Apl = Ae + Ao, Ami = Ae - Ao;
    float Bpl = Be + Bo, Bmi = Be - Bo;
    op[(size_t)H * WW] = Apl - Bpl;
    if constexpr (H != 64)           op[(size_t)(128 - H) * WW] = Ami + Bmi;
    if constexpr (H >= 1)            op[(size_t)(256 - H) * WW] = Apl + Bpl;
    if constexpr (H >= 1 && H != 64) op[(size_t)(128 + H) * WW] = Ami - Bmi;
}

template <int... Hs>
__device__ __forceinline__ void k3_all(const float* pre, const float* pim,
                                       float* __restrict__ op,
                                       std::integer_sequence<int, Hs...>) {
    (k3_one<Hs>(pre, pim, op, std::make_integer_sequence<int, KM>{}), ...);
}

// ---------------------------------------------------------------------------
// K23 (fused): per block bo = b*COUT+o
//   Phase A: blk[r,c] = sum_i S[b,i,r]*w[i,o,r,c]  (complex, pre-scaled);
//            stored packed as float4 {bre,bre,-bim,bim}.
//   Phase B: pp[r] = {ReP, ImP},  P[r,w] = sum_c blk[r,c]*e^{+2pi i c w/256}
//   Phase C: fully unrolled immediate-trig inverse h-DFT with 4-way fold.
// ---------------------------------------------------------------------------
__global__ __launch_bounds__(256, 4) void k23(const float* __restrict__ wr,
                                              const float* __restrict__ wi,
                                              float* __restrict__ out) {
    int bo = blockIdx.x;       // b*COUT + o
    int b  = bo >> 5, o = bo & 31;
    int t  = threadIdx.x;      // 0..255

    __shared__ float  sSre[CIN * KM], sSim[CIN * KM];  // [i][r]
    __shared__ float4 sBq[KM * KM];                    // [r][c] {bre,bre,-bim,bim}

    for (int idx = t; idx < CIN * KM; idx += 256) {
        sSre[idx] = g_Sre[b * CIN * KM + idx];
        sSim[idx] = g_Sim[b * CIN * KM + idx];
    }
    __syncthreads();

    // Phase A: blk, thread = r*16 + c
    {
        int r = t >> 4, c = t & 15;
        float bre = 0.f, bim = 0.f;
        for (int i = 0; i < CIN; i++) {
            float sre = sSre[i * KM + r], sim = sSim[i * KM + r];
            size_t widx = (((size_t)i * COUT + o) * KM + r) * KM + c;
            float wre = wr[widx], wim = wi[widx];
            bre = fmaf(sre, wre, bre);  bre = fmaf(-sim, wim, bre);
            bim = fmaf(sre, wim, bim);  bim = fmaf(sim, wre, bim);
        }
        float a = (c == 0 ? 1.0f : 2.0f) * (1.0f / 256.0f);
        bre *= a;
        bim *= a;
        sBq[t] = make_float4(bre, bre, -bim, bim);
    }
    __syncthreads();

    // Phase B: packed pp[r] = {ReP, ImP}, thread = w; c outer, r inner
    int w = t;
    unsigned long long pp[KM];
#pragma unroll
    for (int r = 0; r < KM; r++) pp[r] = 0ULL;
#pragma unroll
    for (int c = 0; c < KM; c++) {
        float s, cv;
        sincospif((float)(c * w) / 128.0f, &s, &cv);
        unsigned long long P1 = pack2(cv, s);   // {tc, ts}
        unsigned long long P2 = pack2(s, cv);   // {ts, tc}
#pragma unroll
        for (int r = 0; r < KM; r++) {
            ulonglong2 bv = *reinterpret_cast<const ulonglong2*>(&sBq[r * KM + c]);
            // {pre,pim} += {bre,bre}*{tc,ts}  then  += {-bim,bim}*{ts,tc}
            FMA2(pp[r], bv.x, P1, pp[r]);
            FMA2(pp[r], bv.y, P2, pp[r]);
        }
    }

    // Unpack to scalar register arrays for the immediate-FFMA phase C
    float pre[KM], pim[KM];
#pragma unroll
    for (int r = 0; r < KM; r++) unpack2(pp[r], pre[r], pim[r]);

    float* op = out + (size_t)bo * HH * WW + w;
    k3_all(pre, pim, op, std::make_integer_sequence<int, 65>{});
}

// ---------------------------------------------------------------------------
extern "C" void kernel_launch(void* const* d_in, const int* in_sizes, int n_in,
                              void* d_out, int out_size) {
    const float* x  = (const float*)d_in[0];
    const float* wr = (const float*)d_in[1];
    const float* wi = (const float*)d_in[2];
    float* out = (float*)d_out;

    k1_S<<<BB * CIN, 256>>>(x);
    k23<<<BB * COUT, 256>>>(wr, wi, out);
}